// round 6
// baseline (speedup 1.0000x reference)
#include <cuda_runtime.h>
#include <cuda_bf16.h>

// WaveletTransformLayer: x (B=128, T=2048, F=32) f32.
// Per (b,f): d1 (2047) | d2 (2044) | d3 (2037) | ma3 (2037), each / T.
// Collapsed FIR taps over x[t..t+11]:
//   d1[t] = (x1-x0)/2 ; ma2 = [1,2,2,2,1]/8 ; ma3 = [1,3,5,7,8,8,8,8,7,5,3,1]/64
//   d2[t] = (x3+x4)/2 - ma2[t] ; d3[t] = ma2[t+7] - ma3[t]
//
// R6: R5 kernel made persistent. Grid = 148*12 = 1776 (exactly one wave at
// 12 blocks/SM); grid-stride loop over the 2048 (tile,b) units kills the
// 272-block 15%-occupancy straggler wave that dominated R5's profile.

#define T_LEN   2048
#define F_DIM   32
#define TT      128
#define NTILES  (T_LEN / TT)     // 16
#define NUNITS  (NTILES * 128)   // 2048
#define HALO    12
#define LOADT   (TT + HALO)      // 140
#define PITCH   33               // conflict-free for STS.32 fill and LDS.32 compute
#define OUT_PER_F 8165
#define SEG1    2047
#define SEG2    4091
#define SEG3    6128
#define LIM1    2047
#define LIM2    2044
#define LIM3    2037

#define NSM     148
#define BLKSM   12
#define GRID    (NSM * BLKSM)    // 1776

__global__ __launch_bounds__(128, BLKSM)
void wavelet_kernel(const float* __restrict__ x, float* __restrict__ out) {
    __shared__ float xs[LOADT * PITCH];   // 140*33*4 = 18480 B

    const int tid = threadIdx.x;          // 0..127

    const float inv   = 1.0f / 2048.0f;
    const float inv2  = inv * 0.5f;
    const float inv8  = inv * 0.125f;
    const float inv64 = inv * 0.015625f;

    for (int u = blockIdx.x; u < NUNITS; u += GRID) {
        const int tile = u & (NTILES - 1);   // 0..15
        const int b    = u >> 4;             // 0..127
        const int t0   = tile * TT;

        // ---- Fill: LDG.128 (t-major, f contiguous) -> 4x STS.32, conflict-free ----
        const float4* gsrc = (const float4*)(x + (size_t)b * (T_LEN * F_DIM)
                                               + (size_t)t0 * F_DIM);
        if (tile != NTILES - 1) {
            #pragma unroll
            for (int k = 0; k < 9; ++k) {
                int i = tid + k * 128;
                if (i < LOADT * 8) {          // 1120 vec4s
                    int tt = i >> 3;
                    int f4 = (i & 7) << 2;
                    float4 v = gsrc[i];
                    float* d = &xs[tt * PITCH + f4];
                    d[0] = v.x; d[1] = v.y; d[2] = v.z; d[3] = v.w;
                }
            }
        } else {
            #pragma unroll
            for (int k = 0; k < 9; ++k) {
                int i = tid + k * 128;
                if (i < LOADT * 8) {
                    int tt = i >> 3;
                    int f4 = (i & 7) << 2;
                    float4 v = make_float4(0.f, 0.f, 0.f, 0.f);
                    if (t0 + tt < T_LEN) v = gsrc[i];
                    float* d = &xs[tt * PITCH + f4];
                    d[0] = v.x; d[1] = v.y; d[2] = v.z; d[3] = v.w;
                }
            }
        }
        __syncthreads();

        // ---- Compute: thread = t (lane-contiguous -> coalesced stores), loop f ----
        const int t  = tid;
        const int tg = t0 + t;
        float* outb = out + (size_t)b * (F_DIM * OUT_PER_F);

        if (t0 + TT <= LIM3) {   // tiles 0..14: all stores unconditional
            #pragma unroll 2
            for (int f = 0; f < F_DIM; ++f) {
                const float* s = xs + t * PITCH + f;
                float x0  = s[0 * PITCH],  x1 = s[1 * PITCH],  x2  = s[2 * PITCH];
                float x3  = s[3 * PITCH],  x4 = s[4 * PITCH],  x5  = s[5 * PITCH];
                float x6  = s[6 * PITCH],  x7 = s[7 * PITCH],  x8  = s[8 * PITCH];
                float x9  = s[9 * PITCH], x10 = s[10 * PITCH], x11 = s[11 * PITCH];

                float d1  = (x1 - x0) * inv2;
                float m2a = x0 + x4 + 2.0f * (x1 + x2 + x3);
                float d2  = (x3 + x4) * inv2 - m2a * inv8;
                float m2b = x7 + x11 + 2.0f * (x8 + x9 + x10);
                float m3  = (x0 + x11) + 3.0f * (x1 + x10) + 5.0f * (x2 + x9)
                          + 7.0f * (x3 + x8) + 8.0f * (x4 + x5 + x6 + x7);
                float d3  = m2b * inv8 - m3 * inv64;
                float ma3 = m3 * inv64;

                float* of = outb + (size_t)f * OUT_PER_F;
                of[tg]        = d1;
                of[SEG1 + tg] = d2;
                of[SEG2 + tg] = d3;
                of[SEG3 + tg] = ma3;
            }
        } else {                 // tile 15: predicated stores
            const bool w1 = (tg < LIM1);
            const bool w2 = (tg < LIM2);
            const bool w3 = (tg < LIM3);
            #pragma unroll 2
            for (int f = 0; f < F_DIM; ++f) {
                const float* s = xs + t * PITCH + f;
                float x0  = s[0 * PITCH],  x1 = s[1 * PITCH],  x2  = s[2 * PITCH];
                float x3  = s[3 * PITCH],  x4 = s[4 * PITCH],  x5  = s[5 * PITCH];
                float x6  = s[6 * PITCH],  x7 = s[7 * PITCH],  x8  = s[8 * PITCH];
                float x9  = s[9 * PITCH], x10 = s[10 * PITCH], x11 = s[11 * PITCH];

                float d1  = (x1 - x0) * inv2;
                float m2a = x0 + x4 + 2.0f * (x1 + x2 + x3);
                float d2  = (x3 + x4) * inv2 - m2a * inv8;
                float m2b = x7 + x11 + 2.0f * (x8 + x9 + x10);
                float m3  = (x0 + x11) + 3.0f * (x1 + x10) + 5.0f * (x2 + x9)
                          + 7.0f * (x3 + x8) + 8.0f * (x4 + x5 + x6 + x7);
                float d3  = m2b * inv8 - m3 * inv64;
                float ma3 = m3 * inv64;

                float* of = outb + (size_t)f * OUT_PER_F;
                if (w1) of[tg]        = d1;
                if (w2) of[SEG1 + tg] = d2;
                if (w3) {
                    of[SEG2 + tg] = d3;
                    of[SEG3 + tg] = ma3;
                }
            }
        }
        __syncthreads();   // protect smem reuse across grid-stride iterations
    }
}

extern "C" void kernel_launch(void* const* d_in, const int* in_sizes, int n_in,
                              void* d_out, int out_size) {
    const float* x = (const float*)d_in[0];
    float* out = (float*)d_out;
    wavelet_kernel<<<GRID, 128>>>(x, out);
}